// round 1
// baseline (speedup 1.0000x reference)
#include <cuda_runtime.h>
#include <math.h>

#define HIDDEN 1536
#define NHEADS 12
#define HDIM 128
#define MLPH 6144
#define TXT 256
#define LX 4352
#define NC 20
#define LC 4116
#define NROWS 4372          // LX + NC
#define W1OUT 10752         // 3*HIDDEN + MLPH
#define CCW 7680            // HIDDEN + MLPH

// ---------------- scratch (static device globals; no runtime allocation) ---
static __device__ float g_mod[3 * HIDDEN];
static __device__ float g_xm[(size_t)NROWS * HIDDEN];
static __device__ float g_h[(size_t)NROWS * W1OUT];
static __device__ float g_q1[(size_t)NHEADS * LX * HDIM];
static __device__ float g_k1[(size_t)NHEADS * LX * HDIM];
static __device__ float g_vt1[(size_t)NHEADS * HDIM * LX];
static __device__ float g_q2[(size_t)NHEADS * NC * HDIM];
static __device__ float g_k2[(size_t)NHEADS * LC * HDIM];
static __device__ float g_vt2[(size_t)NHEADS * HDIM * LC];
static __device__ float g_s1[(size_t)NHEADS * LX * LX];   // 909 MB logits
static __device__ float g_s2[(size_t)NHEADS * NC * LC];
static __device__ float g_cc[(size_t)NROWS * CCW];
static __device__ float g_out[(size_t)NROWS * HIDDEN];

// ---------------- reductions ----------------------------------------------
__device__ __forceinline__ float warp_sum(float v) {
    #pragma unroll
    for (int o = 16; o > 0; o >>= 1) v += __shfl_xor_sync(0xffffffffu, v, o);
    return v;
}
__device__ __forceinline__ float warp_max(float v) {
    #pragma unroll
    for (int o = 16; o > 0; o >>= 1) v = fmaxf(v, __shfl_xor_sync(0xffffffffu, v, o));
    return v;
}

template <int NT>
__device__ __forceinline__ float block_sum(float v, float* sbuf) {
    v = warp_sum(v);
    int lane = threadIdx.x & 31, w = threadIdx.x >> 5;
    if (lane == 0) sbuf[w] = v;
    __syncthreads();
    if (threadIdx.x < 32) {
        float x = (threadIdx.x < NT / 32) ? sbuf[threadIdx.x] : 0.f;
        x = warp_sum(x);
        if (threadIdx.x == 0) sbuf[0] = x;
    }
    __syncthreads();
    float r = sbuf[0];
    __syncthreads();
    return r;
}

template <int NT>
__device__ __forceinline__ float block_max(float v, float* sbuf) {
    v = warp_max(v);
    int lane = threadIdx.x & 31, w = threadIdx.x >> 5;
    if (lane == 0) sbuf[w] = v;
    __syncthreads();
    if (threadIdx.x < 32) {
        float x = (threadIdx.x < NT / 32) ? sbuf[threadIdx.x] : -1e30f;
        x = warp_max(x);
        if (threadIdx.x == 0) sbuf[0] = x;
    }
    __syncthreads();
    float r = sbuf[0];
    __syncthreads();
    return r;
}

// ---------------- generic C = alpha*A*B^T + bias (A:[M,K], B:[N,K]) --------
// 128x128 tile, BK=8, 256 threads, 8x8 per thread, batched via z with strides.
__global__ void __launch_bounds__(256) sgemm_abt(
    const float* __restrict__ A, int lda, long long sA,
    const float* __restrict__ B, int ldb, long long sB,
    float* __restrict__ C, int ldc, long long sC,
    int M, int N, int K, float alpha, const float* __restrict__ bias)
{
    __shared__ float As[8][128];
    __shared__ float Bs[8][128];
    int bz = blockIdx.z;
    A += (size_t)sA * bz;
    B += (size_t)sB * bz;
    C += (size_t)sC * bz;
    int m0 = blockIdx.y * 128;
    int n0 = blockIdx.x * 128;
    int tid = threadIdx.x;
    int tx = tid & 15, ty = tid >> 4;
    int lrow = tid >> 1;
    int lcol = (tid & 1) * 4;

    float acc[8][8];
    #pragma unroll
    for (int i = 0; i < 8; i++)
        #pragma unroll
        for (int j = 0; j < 8; j++) acc[i][j] = 0.f;

    for (int k0 = 0; k0 < K; k0 += 8) {
        float4 av = make_float4(0.f, 0.f, 0.f, 0.f);
        float4 bv = make_float4(0.f, 0.f, 0.f, 0.f);
        if (m0 + lrow < M && k0 + lcol < K)
            av = *reinterpret_cast<const float4*>(A + (size_t)(m0 + lrow) * lda + k0 + lcol);
        if (n0 + lrow < N && k0 + lcol < K)
            bv = *reinterpret_cast<const float4*>(B + (size_t)(n0 + lrow) * ldb + k0 + lcol);
        As[lcol + 0][lrow] = av.x; As[lcol + 1][lrow] = av.y;
        As[lcol + 2][lrow] = av.z; As[lcol + 3][lrow] = av.w;
        Bs[lcol + 0][lrow] = bv.x; Bs[lcol + 1][lrow] = bv.y;
        Bs[lcol + 2][lrow] = bv.z; Bs[lcol + 3][lrow] = bv.w;
        __syncthreads();
        #pragma unroll
        for (int k = 0; k < 8; k++) {
            float ra[8], rb[8];
            #pragma unroll
            for (int i = 0; i < 8; i++) ra[i] = As[k][ty + 16 * i];
            #pragma unroll
            for (int j = 0; j < 8; j++) rb[j] = Bs[k][tx + 16 * j];
            #pragma unroll
            for (int i = 0; i < 8; i++)
                #pragma unroll
                for (int j = 0; j < 8; j++)
                    acc[i][j] = fmaf(ra[i], rb[j], acc[i][j]);
        }
        __syncthreads();
    }

    #pragma unroll
    for (int i = 0; i < 8; i++) {
        int m = m0 + ty + 16 * i;
        if (m >= M) continue;
        #pragma unroll
        for (int j = 0; j < 8; j++) {
            int n = n0 + tx + 16 * j;
            if (n >= N) continue;
            float v = alpha * acc[i][j];
            if (bias) v += bias[n];
            C[(size_t)m * ldc + n] = v;
        }
    }
}

// ---------------- modulation: m = silu(vec) @ mod_w^T + mod_b --------------
__global__ void __launch_bounds__(128) mod_kernel(
    const float* __restrict__ vec, const float* __restrict__ mod_w,
    const float* __restrict__ mod_b)
{
    int n = blockIdx.x * 4 + (threadIdx.x >> 5);
    if (n >= 3 * HIDDEN) return;
    int lane = threadIdx.x & 31;
    const float* wrow = mod_w + (size_t)n * HIDDEN;
    float acc = 0.f;
    for (int k = lane; k < HIDDEN; k += 32) {
        float xv = vec[k];
        float s = xv / (1.f + __expf(-xv));
        acc = fmaf(s, wrow[k], acc);
    }
    acc = warp_sum(acc);
    if (lane == 0) g_mod[n] = acc + mod_b[n];
}

// ---------------- layernorm + modulate (rows 0..LX-1 = x, rest concepts) ---
__global__ void __launch_bounds__(256) ln_mod_kernel(
    const float* __restrict__ x, const float* __restrict__ concepts)
{
    __shared__ float sbuf[8];
    int row = blockIdx.x;
    const float* src = (row < LX) ? (x + (size_t)row * HIDDEN)
                                  : (concepts + (size_t)(row - LX) * HIDDEN);
    int tid = threadIdx.x;
    float v[6];
    float s = 0.f;
    #pragma unroll
    for (int i = 0; i < 6; i++) { v[i] = src[tid + 256 * i]; s += v[i]; }
    s = block_sum<256>(s, sbuf);
    float mu = s * (1.0f / 1536.0f);
    float s2 = 0.f;
    #pragma unroll
    for (int i = 0; i < 6; i++) { float d = v[i] - mu; s2 = fmaf(d, d, s2); }
    s2 = block_sum<256>(s2, sbuf);
    float rstd = rsqrtf(s2 * (1.0f / 1536.0f) + 1e-6f);
    #pragma unroll
    for (int i = 0; i < 6; i++) {
        int j = tid + 256 * i;
        float sc = g_mod[HIDDEN + j];
        float sh = g_mod[j];
        g_xm[(size_t)row * HIDDEN + j] = (1.f + sc) * ((v[i] - mu) * rstd) + sh;
    }
}

// ---------------- RoPE helper (pair exchange via shfl) ---------------------
__device__ __forceinline__ float rope_pair(float a, const float* __restrict__ petab,
                                           int tok, int d)
{
    float b = __shfl_xor_sync(0xffffffffu, a, 1);
    int i = d >> 1;
    const float* p = petab + ((size_t)tok * 64 + i) * 4;
    // even lane: a = t[2i], b = t[2i+1]; odd lane: a = t[2i+1], b = t[2i]
    if ((d & 1) == 0) return fmaf(p[0], a, p[1] * b);
    else              return fmaf(p[2], b, p[3] * a);
}

// ---------------- attention prep for x tokens ------------------------------
// Writes Q1/K1 (roped with pe), V^T; for image tokens also K2 (roped with
// concept_pe) and V2^T — reusing shared pre-RoPE values between both blocks.
__global__ void __launch_bounds__(128) attn_prep1(
    const float* __restrict__ pe, const float* __restrict__ cpe,
    const float* __restrict__ q_scale, const float* __restrict__ k_scale)
{
    __shared__ float sbuf[4];
    int t = blockIdx.x, h = blockIdx.y, d = threadIdx.x;
    const float* hrow = g_h + (size_t)t * W1OUT;
    float q = hrow[h * HDIM + d];
    float k = hrow[HIDDEN + h * HDIM + d];
    float v = hrow[2 * HIDDEN + h * HDIM + d];
    float msq = block_sum<128>(q * q, sbuf) * (1.f / 128.f);
    float msk = block_sum<128>(k * k, sbuf) * (1.f / 128.f);
    float qn = q * rsqrtf(msq + 1e-6f) * q_scale[d];
    float kn = k * rsqrtf(msk + 1e-6f) * k_scale[d];
    g_q1[((size_t)h * LX + t) * HDIM + d] = rope_pair(qn, pe, t, d);
    g_k1[((size_t)h * LX + t) * HDIM + d] = rope_pair(kn, pe, t, d);
    g_vt1[((size_t)h * HDIM + d) * LX + t] = v;
    if (t >= TXT) {
        int j = NC + (t - TXT);
        g_k2[((size_t)h * LC + j) * HDIM + d] = rope_pair(kn, cpe, j, d);
        g_vt2[((size_t)h * HDIM + d) * LC + j] = v;
    }
}

// ---------------- attention prep for concept tokens ------------------------
__global__ void __launch_bounds__(128) attn_prep2(
    const float* __restrict__ cpe,
    const float* __restrict__ q_scale, const float* __restrict__ k_scale)
{
    __shared__ float sbuf[4];
    int i = blockIdx.x, h = blockIdx.y, d = threadIdx.x;
    const float* hrow = g_h + (size_t)(LX + i) * W1OUT;
    float q = hrow[h * HDIM + d];
    float k = hrow[HIDDEN + h * HDIM + d];
    float v = hrow[2 * HIDDEN + h * HDIM + d];
    float msq = block_sum<128>(q * q, sbuf) * (1.f / 128.f);
    float msk = block_sum<128>(k * k, sbuf) * (1.f / 128.f);
    float qn = q * rsqrtf(msq + 1e-6f) * q_scale[d];
    float kn = k * rsqrtf(msk + 1e-6f) * k_scale[d];
    g_q2[((size_t)h * NC + i) * HDIM + d] = rope_pair(qn, cpe, i, d);
    g_k2[((size_t)h * LC + i) * HDIM + d] = rope_pair(kn, cpe, i, d);
    g_vt2[((size_t)h * HDIM + d) * LC + i] = v;
}

// ---------------- row softmax (ncol <= 4352, 17 regs/thread) ---------------
__global__ void __launch_bounds__(256) softmax_rows(float* __restrict__ S, int ncol)
{
    __shared__ float sbuf[8];
    float* row = S + (size_t)blockIdx.x * ncol;
    int tid = threadIdx.x;
    float v[17];
    float mx = -1e30f;
    #pragma unroll
    for (int i = 0; i < 17; i++) {
        int c = tid + 256 * i;
        v[i] = (c < ncol) ? row[c] : -1e30f;
        mx = fmaxf(mx, v[i]);
    }
    mx = block_max<256>(mx, sbuf);
    float s = 0.f;
    #pragma unroll
    for (int i = 0; i < 17; i++) { v[i] = __expf(v[i] - mx); s += v[i]; }
    s = block_sum<256>(s, sbuf);
    float inv = 1.f / s;
    #pragma unroll
    for (int i = 0; i < 17; i++) {
        int c = tid + 256 * i;
        if (c < ncol) row[c] = v[i] * inv;
    }
}

// ---------------- gelu(tanh) on mlp part into concat buffer ----------------
__global__ void __launch_bounds__(256) gelu_kernel()
{
    size_t idx = (size_t)blockIdx.x * 256 + threadIdx.x;
    if (idx >= (size_t)NROWS * MLPH) return;
    size_t r = idx / MLPH;
    int c = (int)(idx % MLPH);
    float xv = g_h[r * W1OUT + 3 * HIDDEN + c];
    float inner = 0.7978845608028654f * fmaf(0.044715f * xv * xv, xv, xv);
    g_cc[r * CCW + HIDDEN + c] = 0.5f * xv * (1.f + tanhf(inner));
}

// ---------------- residual: out = base + gate * block_out ------------------
__global__ void __launch_bounds__(256) final_kernel(
    const float* __restrict__ x, const float* __restrict__ concepts,
    float* __restrict__ out)
{
    size_t idx = (size_t)blockIdx.x * 256 + threadIdx.x;
    if (idx >= (size_t)NROWS * HIDDEN) return;
    int c = (int)(idx % HIDDEN);
    size_t r = idx / HIDDEN;
    float base = (r < LX) ? x[idx] : concepts[idx - (size_t)LX * HIDDEN];
    out[idx] = fmaf(g_mod[2 * HIDDEN + c], g_out[idx], base);
}

// ---------------------------------------------------------------------------
extern "C" void kernel_launch(void* const* d_in, const int* in_sizes, int n_in,
                              void* d_out, int out_size)
{
    const float* x        = (const float*)d_in[0];
    const float* concepts = (const float*)d_in[1];
    const float* vec      = (const float*)d_in[2];
    const float* pe       = (const float*)d_in[3];
    const float* cpe      = (const float*)d_in[4];
    const float* w1       = (const float*)d_in[5];
    const float* b1       = (const float*)d_in[6];
    const float* w2       = (const float*)d_in[7];
    const float* b2       = (const float*)d_in[8];
    const float* q_scale  = (const float*)d_in[9];
    const float* k_scale  = (const float*)d_in[10];
    const float* mod_w    = (const float*)d_in[11];
    const float* mod_b    = (const float*)d_in[12];
    float* out = (float*)d_out;

    void* p;
    cudaGetSymbolAddress(&p, g_xm);  float* xm   = (float*)p;
    cudaGetSymbolAddress(&p, g_h);   float* hbuf = (float*)p;
    cudaGetSymbolAddress(&p, g_q1);  float* q1b  = (float*)p;
    cudaGetSymbolAddress(&p, g_k1);  float* k1b  = (float*)p;
    cudaGetSymbolAddress(&p, g_vt1); float* vt1b = (float*)p;
    cudaGetSymbolAddress(&p, g_q2);  float* q2b  = (float*)p;
    cudaGetSymbolAddress(&p, g_k2);  float* k2b  = (float*)p;
    cudaGetSymbolAddress(&p, g_vt2); float* vt2b = (float*)p;
    cudaGetSymbolAddress(&p, g_s1);  float* s1b  = (float*)p;
    cudaGetSymbolAddress(&p, g_s2);  float* s2b  = (float*)p;
    cudaGetSymbolAddress(&p, g_cc);  float* ccb  = (float*)p;
    cudaGetSymbolAddress(&p, g_out); float* outb = (float*)p;

    const float scl = 0.08838834764831845f;  // 1/sqrt(128)

    // modulation vector (shift | scale | gate)
    mod_kernel<<<(3 * HIDDEN + 3) / 4, 128>>>(vec, mod_w, mod_b);
    // layernorm + modulate all 4372 unique rows (x rows + concept rows)
    ln_mod_kernel<<<NROWS, 256>>>(x, concepts);
    // GEMM1: h = xm @ w1^T + b1   [4372 x 10752]
    sgemm_abt<<<dim3((W1OUT + 127) / 128, (NROWS + 127) / 128, 1), 256>>>(
        xm, HIDDEN, 0, w1, HIDDEN, 0, hbuf, W1OUT, 0,
        NROWS, W1OUT, HIDDEN, 1.f, b1);
    // rmsnorm + rope; block2 K/V for image tokens derived from shared values
    attn_prep1<<<dim3(LX, NHEADS), 128>>>(pe, cpe, q_scale, k_scale);
    attn_prep2<<<dim3(NC, NHEADS), 128>>>(cpe, q_scale, k_scale);
    // block1 attention: S1 = scl * Q1 K1^T ; softmax ; O1 = S1 V -> cc[:, h*128..]
    sgemm_abt<<<dim3(LX / 128, LX / 128, NHEADS), 256>>>(
        q1b, HDIM, (long long)LX * HDIM, k1b, HDIM, (long long)LX * HDIM,
        s1b, LX, (long long)LX * LX, LX, LX, HDIM, scl, nullptr);
    softmax_rows<<<NHEADS * LX, 256>>>(s1b, LX);
    sgemm_abt<<<dim3(1, LX / 128, NHEADS), 256>>>(
        s1b, LX, (long long)LX * LX, vt1b, LX, (long long)HDIM * LX,
        ccb, CCW, HDIM, LX, HDIM, LX, 1.f, nullptr);
    // block2 attention (20 queries over 4116 keys)
    sgemm_abt<<<dim3((LC + 127) / 128, 1, NHEADS), 256>>>(
        q2b, HDIM, (long long)NC * HDIM, k2b, HDIM, (long long)LC * HDIM,
        s2b, LC, (long long)NC * LC, NC, LC, HDIM, scl, nullptr);
    softmax_rows<<<NHEADS * NC, 256>>>(s2b, LC);
    sgemm_abt<<<dim3(1, 1, NHEADS), 256>>>(
        s2b, LC, (long long)NC * LC, vt2b, LC, (long long)HDIM * LC,
        ccb + (size_t)LX * CCW, CCW, HDIM, NC, HDIM, LC, 1.f, nullptr);
    // gelu on mlp half into concat buffer (all 4372 rows)
    gelu_kernel<<<(unsigned)(((size_t)NROWS * MLPH + 255) / 256), 256>>>();
    // GEMM2: out = cc @ w2^T + b2   [4372 x 1536]
    sgemm_abt<<<dim3((HIDDEN + 127) / 128, (NROWS + 127) / 128, 1), 256>>>(
        ccb, CCW, 0, w2, CCW, 0, outb, HIDDEN, 0,
        NROWS, HIDDEN, CCW, 1.f, b2);
    // residual + gate; write x_out then concepts_out
    final_kernel<<<(unsigned)(((size_t)NROWS * HIDDEN + 255) / 256), 256>>>(
        x, concepts, out);
}

// round 3
// speedup vs baseline: 2.1709x; 2.1709x over previous
#include <cuda_runtime.h>
#include <cuda_bf16.h>
#include <math.h>
#include <stdint.h>

#define HIDDEN 1536
#define NHEADS 12
#define HDIM 128
#define MLPH 6144
#define TXT 256
#define LX 4352
#define NC 20
#define LC 4116
#define NROWS 4372          // LX + NC
#define W1OUT 10752         // 3*HIDDEN + MLPH
#define CCW 7680            // HIDDEN + MLPH

// ---------------- scratch (static device globals; no runtime allocation) ---
static __device__ float g_mod[3 * HIDDEN];
static __device__ float g_xm[(size_t)NROWS * HIDDEN];
static __device__ float g_h[(size_t)NROWS * W1OUT];
static __device__ float g_q1[(size_t)NHEADS * LX * HDIM];
static __device__ float g_k1[(size_t)NHEADS * LX * HDIM];
static __device__ float g_vt1[(size_t)NHEADS * HDIM * LX];
static __device__ float g_q2[(size_t)NHEADS * NC * HDIM];
static __device__ float g_k2[(size_t)NHEADS * LC * HDIM];
static __device__ float g_vt2[(size_t)NHEADS * HDIM * LC];
static __device__ float g_s1[(size_t)NHEADS * LX * LX];   // 909 MB logits
static __device__ float g_s2[(size_t)NHEADS * NC * LC];
static __device__ float g_cc[(size_t)NROWS * CCW];
static __device__ float g_out[(size_t)NROWS * HIDDEN];

// ---------------- reductions ----------------------------------------------
__device__ __forceinline__ float warp_sum(float v) {
    #pragma unroll
    for (int o = 16; o > 0; o >>= 1) v += __shfl_xor_sync(0xffffffffu, v, o);
    return v;
}
__device__ __forceinline__ float warp_max(float v) {
    #pragma unroll
    for (int o = 16; o > 0; o >>= 1) v = fmaxf(v, __shfl_xor_sync(0xffffffffu, v, o));
    return v;
}

template <int NT>
__device__ __forceinline__ float block_sum(float v, float* sbuf) {
    v = warp_sum(v);
    int lane = threadIdx.x & 31, w = threadIdx.x >> 5;
    if (lane == 0) sbuf[w] = v;
    __syncthreads();
    if (threadIdx.x < 32) {
        float x = (threadIdx.x < NT / 32) ? sbuf[threadIdx.x] : 0.f;
        x = warp_sum(x);
        if (threadIdx.x == 0) sbuf[0] = x;
    }
    __syncthreads();
    float r = sbuf[0];
    __syncthreads();
    return r;
}

template <int NT>
__device__ __forceinline__ float block_max(float v, float* sbuf) {
    v = warp_max(v);
    int lane = threadIdx.x & 31, w = threadIdx.x >> 5;
    if (lane == 0) sbuf[w] = v;
    __syncthreads();
    if (threadIdx.x < 32) {
        float x = (threadIdx.x < NT / 32) ? sbuf[threadIdx.x] : -1e30f;
        x = warp_max(x);
        if (threadIdx.x == 0) sbuf[0] = x;
    }
    __syncthreads();
    float r = sbuf[0];
    __syncthreads();
    return r;
}

// ======================= HMMA helpers (mma.sync, sm_80+) ===================
__device__ __forceinline__ uint32_t smem_u32(const void* p) {
    uint32_t a;
    asm("{ .reg .u64 t; cvta.to.shared.u64 t, %1; cvt.u32.u64 %0, t; }"
        : "=r"(a) : "l"(p));
    return a;
}
__device__ __forceinline__ void ldsm4(uint32_t* r, uint32_t addr) {
    asm volatile("ldmatrix.sync.aligned.m8n8.x4.shared.b16 {%0,%1,%2,%3}, [%4];"
                 : "=r"(r[0]), "=r"(r[1]), "=r"(r[2]), "=r"(r[3]) : "r"(addr));
}
__device__ __forceinline__ void mma_bf16(float* c, const uint32_t* a,
                                         uint32_t b0, uint32_t b1) {
    asm volatile(
        "mma.sync.aligned.m16n8k16.row.col.f32.bf16.bf16.f32 "
        "{%0,%1,%2,%3}, {%4,%5,%6,%7}, {%8,%9}, {%0,%1,%2,%3};"
        : "+f"(c[0]), "+f"(c[1]), "+f"(c[2]), "+f"(c[3])
        : "r"(a[0]), "r"(a[1]), "r"(a[2]), "r"(a[3]), "r"(b0), "r"(b1));
}

// split fp32 -> (hi, lo) bf16 pairs, 4 at a time, packed 2-per-u32
__device__ __forceinline__ void split4(float4 v, uint2& h, uint2& l) {
    float f0 = v.x, f1 = v.y, f2 = v.z, f3 = v.w;
    __nv_bfloat16 h0 = __float2bfloat16(f0), h1 = __float2bfloat16(f1);
    __nv_bfloat16 h2 = __float2bfloat16(f2), h3 = __float2bfloat16(f3);
    __nv_bfloat16 l0 = __float2bfloat16(f0 - __bfloat162float(h0));
    __nv_bfloat16 l1 = __float2bfloat16(f1 - __bfloat162float(h1));
    __nv_bfloat16 l2 = __float2bfloat16(f2 - __bfloat162float(h2));
    __nv_bfloat16 l3 = __float2bfloat16(f3 - __bfloat162float(h3));
    __nv_bfloat162 ph0 = __nv_bfloat162(h0, h1), ph1 = __nv_bfloat162(h2, h3);
    __nv_bfloat162 pl0 = __nv_bfloat162(l0, l1), pl1 = __nv_bfloat162(l2, l3);
    h.x = *reinterpret_cast<uint32_t*>(&ph0);
    h.y = *reinterpret_cast<uint32_t*>(&ph1);
    l.x = *reinterpret_cast<uint32_t*>(&pl0);
    l.y = *reinterpret_cast<uint32_t*>(&pl1);
}

// smem layout per stage: A_hi, A_lo, B_hi, B_lo tiles, 128 rows x 32 bf16,
// padded row stride 80 B (40 bf16) -> conflict-free ldmatrix.
#define SPB      80
#define T_BYTES  (128 * SPB)          // 10240
#define AH_OFF   0
#define AL_OFF   (1 * T_BYTES)
#define BH_OFF   (2 * T_BYTES)
#define BL_OFF   (3 * T_BYTES)
#define STAGE_B  (4 * T_BYTES)        // 40960
#define HG_SMEM  (2 * STAGE_B)        // 81920

// ============ HMMA GEMM: C = alpha*A@B^T + bias (split bf16, 3 products) ===
// A:[M,K] lda, B:[N,K] ldb, C:[M,N] ldc; batched via blockIdx.z strides.
// Requires: K % 32 == 0, N % 128 == 0. M may be ragged (guarded).
__global__ void __launch_bounds__(256, 1) hmma_gemm(
    const float* __restrict__ A, int lda, long long sA,
    const float* __restrict__ B, int ldb, long long sB,
    float* __restrict__ C, int ldc, long long sC,
    int M, int N, int K, float alpha, const float* __restrict__ bias)
{
    extern __shared__ char smem[];
    uint32_t sbase = smem_u32(smem);
    int tid = threadIdx.x, wid = tid >> 5, lane = tid & 31;
    int bz = blockIdx.z;
    A += (size_t)sA * bz;
    B += (size_t)sB * bz;
    C += (size_t)sC * bz;
    int m0 = blockIdx.y * 128, n0 = blockIdx.x * 128;

    int warp_m = wid & 3;          // 4 warps along M (32 rows each)
    int warp_n = wid >> 2;         // 2 warps along N (64 cols each)
    int lrow = lane & 15, lhalf = lane >> 4;

    // lane-dependent ldmatrix byte offsets (within a tile region)
    uint32_t a_off[2], b_off[4];
    #pragma unroll
    for (int i = 0; i < 2; ++i)
        a_off[i] = (uint32_t)((warp_m * 32 + i * 16 + lrow) * SPB + lhalf * 16);
    #pragma unroll
    for (int g = 0; g < 4; ++g)
        b_off[g] = (uint32_t)((warp_n * 64 + g * 16 + lrow) * SPB + lhalf * 16);

    float acc[2][8][4];
    #pragma unroll
    for (int i = 0; i < 2; ++i)
        #pragma unroll
        for (int j = 0; j < 8; ++j)
            #pragma unroll
            for (int t = 0; t < 4; ++t) acc[i][j][t] = 0.f;

    int ldr = tid >> 3;            // row 0..31 base for loads (x4 pages)
    int ldc4 = tid & 7;            // float4 col 0..7

    float4 areg[4], breg[4];

    auto load_chunk = [&](int kc) {
        #pragma unroll
        for (int p = 0; p < 4; ++p) {
            int r = ldr + p * 32;
            areg[p] = (m0 + r < M)
                ? *reinterpret_cast<const float4*>(A + (size_t)(m0 + r) * lda + kc + ldc4 * 4)
                : make_float4(0.f, 0.f, 0.f, 0.f);
            breg[p] = *reinterpret_cast<const float4*>(B + (size_t)(n0 + r) * ldb + kc + ldc4 * 4);
        }
    };
    auto store_chunk = [&](int s) {
        char* tb = smem + s * STAGE_B;
        #pragma unroll
        for (int p = 0; p < 4; ++p) {
            int r = ldr + p * 32;
            uint32_t off = (uint32_t)(r * SPB + ldc4 * 8);
            uint2 h, l;
            split4(areg[p], h, l);
            *reinterpret_cast<uint2*>(tb + AH_OFF + off) = h;
            *reinterpret_cast<uint2*>(tb + AL_OFF + off) = l;
            split4(breg[p], h, l);
            *reinterpret_cast<uint2*>(tb + BH_OFF + off) = h;
            *reinterpret_cast<uint2*>(tb + BL_OFF + off) = l;
        }
    };
    auto compute = [&](int s) {
        uint32_t sb = sbase + s * STAGE_B;
        #pragma unroll
        for (int k16 = 0; k16 < 2; ++k16) {
            uint32_t koff = (uint32_t)(k16 * 32);
            uint32_t ah[2][4], al[2][4], bh[4][4], bl[4][4];
            #pragma unroll
            for (int i = 0; i < 2; ++i) {
                ldsm4(ah[i], sb + AH_OFF + a_off[i] + koff);
                ldsm4(al[i], sb + AL_OFF + a_off[i] + koff);
            }
            #pragma unroll
            for (int g = 0; g < 4; ++g) {
                ldsm4(bh[g], sb + BH_OFF + b_off[g] + koff);
                ldsm4(bl[g], sb + BL_OFF + b_off[g] + koff);
            }
            #pragma unroll
            for (int i = 0; i < 2; ++i)
                #pragma unroll
                for (int j = 0; j < 8; ++j) {
                    int g = j >> 1, sI = j & 1;
                    mma_bf16(acc[i][j], ah[i], bh[g][sI], bh[g][sI + 2]);
                    mma_bf16(acc[i][j], al[i], bh[g][sI], bh[g][sI + 2]);
                    mma_bf16(acc[i][j], ah[i], bl[g][sI], bl[g][sI + 2]);
                }
        }
    };

    int nch = K >> 5;
    load_chunk(0);
    store_chunk(0);
    __syncthreads();
    for (int c = 0; c < nch; ++c) {
        if (c + 1 < nch) load_chunk((c + 1) << 5);
        compute(c & 1);
        if (c + 1 < nch) {
            store_chunk((c + 1) & 1);
            __syncthreads();
        }
    }

    // ---- epilogue ----
    int trow = lane >> 2, tc2 = (lane & 3) * 2;
    #pragma unroll
    for (int i = 0; i < 2; ++i) {
        int mbase = m0 + warp_m * 32 + i * 16 + trow;
        #pragma unroll
        for (int half = 0; half < 2; ++half) {
            int m = mbase + half * 8;
            if (m >= M) continue;
            float* crow = C + (size_t)m * ldc;
            #pragma unroll
            for (int j = 0; j < 8; ++j) {
                int n = n0 + warp_n * 64 + j * 8 + tc2;
                float2 v;
                v.x = alpha * acc[i][j][half * 2 + 0];
                v.y = alpha * acc[i][j][half * 2 + 1];
                if (bias) { v.x += bias[n]; v.y += bias[n + 1]; }
                *reinterpret_cast<float2*>(crow + n) = v;
            }
        }
    }
}

// ---------------- SIMT fallback GEMM for tiny block-2 attention ------------
__global__ void __launch_bounds__(256) sgemm_abt(
    const float* __restrict__ A, int lda, long long sA,
    const float* __restrict__ B, int ldb, long long sB,
    float* __restrict__ C, int ldc, long long sC,
    int M, int N, int K, float alpha, const float* __restrict__ bias)
{
    __shared__ float As[8][128];
    __shared__ float Bs[8][128];
    int bz = blockIdx.z;
    A += (size_t)sA * bz;
    B += (size_t)sB * bz;
    C += (size_t)sC * bz;
    int m0 = blockIdx.y * 128;
    int n0 = blockIdx.x * 128;
    int tid = threadIdx.x;
    int tx = tid & 15, ty = tid >> 4;
    int lrow = tid >> 1;
    int lcol = (tid & 1) * 4;

    float acc[8][8];
    #pragma unroll
    for (int i = 0; i < 8; i++)
        #pragma unroll
        for (int j = 0; j < 8; j++) acc[i][j] = 0.f;

    for (int k0 = 0; k0 < K; k0 += 8) {
        float4 av = make_float4(0.f, 0.f, 0.f, 0.f);
        float4 bv = make_float4(0.f, 0.f, 0.f, 0.f);
        if (m0 + lrow < M && k0 + lcol < K)
            av = *reinterpret_cast<const float4*>(A + (size_t)(m0 + lrow) * lda + k0 + lcol);
        if (n0 + lrow < N && k0 + lcol < K)
            bv = *reinterpret_cast<const float4*>(B + (size_t)(n0 + lrow) * ldb + k0 + lcol);
        As[lcol + 0][lrow] = av.x; As[lcol + 1][lrow] = av.y;
        As[lcol + 2][lrow] = av.z; As[lcol + 3][lrow] = av.w;
        Bs[lcol + 0][lrow] = bv.x; Bs[lcol + 1][lrow] = bv.y;
        Bs[lcol + 2][lrow] = bv.z; Bs[lcol + 3][lrow] = bv.w;
        __syncthreads();
        #pragma unroll
        for (int k = 0; k < 8; k++) {
            float ra[8], rb[8];
            #pragma unroll
            for (int i = 0; i < 8; i++) ra[i] = As[k][ty + 16 * i];
            #pragma unroll
            for (int j = 0; j < 8; j++) rb[j] = Bs[k][tx + 16 * j];
            #pragma unroll
            for (int i = 0; i < 8; i++)
                #pragma unroll
                for (int j = 0; j < 8; j++)
                    acc[i][j] = fmaf(ra[i], rb[j], acc[i][j]);
        }
        __syncthreads();
    }

    #pragma unroll
    for (int i = 0; i < 8; i++) {
        int m = m0 + ty + 16 * i;
        if (m >= M) continue;
        #pragma unroll
        for (int j = 0; j < 8; j++) {
            int n = n0 + tx + 16 * j;
            if (n >= N) continue;
            float v = alpha * acc[i][j];
            if (bias) v += bias[n];
            C[(size_t)m * ldc + n] = v;
        }
    }
}

// ---------------- modulation: m = silu(vec) @ mod_w^T + mod_b --------------
__global__ void __launch_bounds__(128) mod_kernel(
    const float* __restrict__ vec, const float* __restrict__ mod_w,
    const float* __restrict__ mod_b)
{
    int n = blockIdx.x * 4 + (threadIdx.x >> 5);
    if (n >= 3 * HIDDEN) return;
    int lane = threadIdx.x & 31;
    const float* wrow = mod_w + (size_t)n * HIDDEN;
    float acc = 0.f;
    for (int k = lane; k < HIDDEN; k += 32) {
        float xv = vec[k];
        float s = xv / (1.f + __expf(-xv));
        acc = fmaf(s, wrow[k], acc);
    }
    acc = warp_sum(acc);
    if (lane == 0) g_mod[n] = acc + mod_b[n];
}

// ---------------- layernorm + modulate -------------------------------------
__global__ void __launch_bounds__(256) ln_mod_kernel(
    const float* __restrict__ x, const float* __restrict__ concepts)
{
    __shared__ float sbuf[8];
    int row = blockIdx.x;
    const float* src = (row < LX) ? (x + (size_t)row * HIDDEN)
                                  : (concepts + (size_t)(row - LX) * HIDDEN);
    int tid = threadIdx.x;
    float v[6];
    float s = 0.f;
    #pragma unroll
    for (int i = 0; i < 6; i++) { v[i] = src[tid + 256 * i]; s += v[i]; }
    s = block_sum<256>(s, sbuf);
    float mu = s * (1.0f / 1536.0f);
    float s2 = 0.f;
    #pragma unroll
    for (int i = 0; i < 6; i++) { float d = v[i] - mu; s2 = fmaf(d, d, s2); }
    s2 = block_sum<256>(s2, sbuf);
    float rstd = rsqrtf(s2 * (1.0f / 1536.0f) + 1e-6f);
    #pragma unroll
    for (int i = 0; i < 6; i++) {
        int j = tid + 256 * i;
        float sc = g_mod[HIDDEN + j];
        float sh = g_mod[j];
        g_xm[(size_t)row * HIDDEN + j] = (1.f + sc) * ((v[i] - mu) * rstd) + sh;
    }
}

// ---------------- RoPE helper (pair exchange via shfl) ---------------------
__device__ __forceinline__ float rope_pair(float a, const float* __restrict__ petab,
                                           int tok, int d)
{
    float b = __shfl_xor_sync(0xffffffffu, a, 1);
    int i = d >> 1;
    const float* p = petab + ((size_t)tok * 64 + i) * 4;
    if ((d & 1) == 0) return fmaf(p[0], a, p[1] * b);
    else              return fmaf(p[2], b, p[3] * a);
}

// ---------------- attention prep for x tokens ------------------------------
__global__ void __launch_bounds__(128) attn_prep1(
    const float* __restrict__ pe, const float* __restrict__ cpe,
    const float* __restrict__ q_scale, const float* __restrict__ k_scale)
{
    __shared__ float sbuf[4];
    int t = blockIdx.x, h = blockIdx.y, d = threadIdx.x;
    const float* hrow = g_h + (size_t)t * W1OUT;
    float q = hrow[h * HDIM + d];
    float k = hrow[HIDDEN + h * HDIM + d];
    float v = hrow[2 * HIDDEN + h * HDIM + d];
    float msq = block_sum<128>(q * q, sbuf) * (1.f / 128.f);
    float msk = block_sum<128>(k * k, sbuf) * (1.f / 128.f);
    float qn = q * rsqrtf(msq + 1e-6f) * q_scale[d];
    float kn = k * rsqrtf(msk + 1e-6f) * k_scale[d];
    g_q1[((size_t)h * LX + t) * HDIM + d] = rope_pair(qn, pe, t, d);
    g_k1[((size_t)h * LX + t) * HDIM + d] = rope_pair(kn, pe, t, d);
    g_vt1[((size_t)h * HDIM + d) * LX + t] = v;
    if (t >= TXT) {
        int j = NC + (t - TXT);
        g_k2[((size_t)h * LC + j) * HDIM + d] = rope_pair(kn, cpe, j, d);
        g_vt2[((size_t)h * HDIM + d) * LC + j] = v;
    }
}

// ---------------- attention prep for concept tokens ------------------------
__global__ void __launch_bounds__(128) attn_prep2(
    const float* __restrict__ cpe,
    const float* __restrict__ q_scale, const float* __restrict__ k_scale)
{
    __shared__ float sbuf[4];
    int i = blockIdx.x, h = blockIdx.y, d = threadIdx.x;
    const float* hrow = g_h + (size_t)(LX + i) * W1OUT;
    float q = hrow[h * HDIM + d];
    float k = hrow[HIDDEN + h * HDIM + d];
    float v = hrow[2 * HIDDEN + h * HDIM + d];
    float msq = block_sum<128>(q * q, sbuf) * (1.f / 128.f);
    float msk = block_sum<128>(k * k, sbuf) * (1.f / 128.f);
    float qn = q * rsqrtf(msq + 1e-6f) * q_scale[d];
    float kn = k * rsqrtf(msk + 1e-6f) * k_scale[d];
    g_q2[((size_t)h * NC + i) * HDIM + d] = rope_pair(qn, cpe, i, d);
    g_k2[((size_t)h * LC + i) * HDIM + d] = rope_pair(kn, cpe, i, d);
    g_vt2[((size_t)h * HDIM + d) * LC + i] = v;
}

// ---------------- row softmax ----------------------------------------------
__global__ void __launch_bounds__(256) softmax_rows(float* __restrict__ S, int ncol)
{
    __shared__ float sbuf[8];
    float* row = S + (size_t)blockIdx.x * ncol;
    int tid = threadIdx.x;
    float v[17];
    float mx = -1e30f;
    #pragma unroll
    for (int i = 0; i < 17; i++) {
        int c = tid + 256 * i;
        v[i] = (c < ncol) ? row[c] : -1e30f;
        mx = fmaxf(mx, v[i]);
    }
    mx = block_max<256>(mx, sbuf);
    float s = 0.f;
    #pragma unroll
    for (int i = 0; i < 17; i++) { v[i] = __expf(v[i] - mx); s += v[i]; }
    s = block_sum<256>(s, sbuf);
    float inv = 1.f / s;
    #pragma unroll
    for (int i = 0; i < 17; i++) {
        int c = tid + 256 * i;
        if (c < ncol) row[c] = v[i] * inv;
    }
}

// ---------------- gelu(tanh) on mlp part into concat buffer ----------------
__global__ void __launch_bounds__(256) gelu_kernel()
{
    size_t idx = (size_t)blockIdx.x * 256 + threadIdx.x;
    if (idx >= (size_t)NROWS * MLPH) return;
    size_t r = idx / MLPH;
    int c = (int)(idx % MLPH);
    float xv = g_h[r * W1OUT + 3 * HIDDEN + c];
    float inner = 0.7978845608028654f * fmaf(0.044715f * xv * xv, xv, xv);
    g_cc[r * CCW + HIDDEN + c] = 0.5f * xv * (1.f + tanhf(inner));
}

// ---------------- residual: out = base + gate * block_out ------------------
__global__ void __launch_bounds__(256) final_kernel(
    const float* __restrict__ x, const float* __restrict__ concepts,
    float* __restrict__ out)
{
    size_t idx = (size_t)blockIdx.x * 256 + threadIdx.x;
    if (idx >= (size_t)NROWS * HIDDEN) return;
    int c = (int)(idx % HIDDEN);
    size_t r = idx / HIDDEN;
    float base = (r < LX) ? x[idx] : concepts[idx - (size_t)LX * HIDDEN];
    out[idx] = fmaf(g_mod[2 * HIDDEN + c], g_out[idx], base);
}

// ---------------------------------------------------------------------------
extern "C" void kernel_launch(void* const* d_in, const int* in_sizes, int n_in,
                              void* d_out, int out_size)
{
    const float* x        = (const float*)d_in[0];
    const float* concepts = (const float*)d_in[1];
    const float* vec      = (const float*)d_in[2];
    const float* pe       = (const float*)d_in[3];
    const float* cpe      = (const float*)d_in[4];
    const float* w1       = (const float*)d_in[5];
    const float* b1       = (const float*)d_in[6];
    const float* w2       = (const float*)d_in[7];
    const float* b2       = (const float*)d_in[8];
    const float* q_scale  = (const float*)d_in[9];
    const float* k_scale  = (const float*)d_in[10];
    const float* mod_w    = (const float*)d_in[11];
    const float* mod_b    = (const float*)d_in[12];
    float* out = (float*)d_out;

    void* p;
    cudaGetSymbolAddress(&p, g_xm);  float* xm   = (float*)p;
    cudaGetSymbolAddress(&p, g_h);   float* hbuf = (float*)p;
    cudaGetSymbolAddress(&p, g_q1);  float* q1b  = (float*)p;
    cudaGetSymbolAddress(&p, g_k1);  float* k1b  = (float*)p;
    cudaGetSymbolAddress(&p, g_vt1); float* vt1b = (float*)p;
    cudaGetSymbolAddress(&p, g_q2);  float* q2b  = (float*)p;
    cudaGetSymbolAddress(&p, g_k2);  float* k2b  = (float*)p;
    cudaGetSymbolAddress(&p, g_vt2); float* vt2b = (float*)p;
    cudaGetSymbolAddress(&p, g_s1);  float* s1b  = (float*)p;
    cudaGetSymbolAddress(&p, g_s2);  float* s2b  = (float*)p;
    cudaGetSymbolAddress(&p, g_cc);  float* ccb  = (float*)p;
    cudaGetSymbolAddress(&p, g_out); float* outb = (float*)p;

    cudaFuncSetAttribute(hmma_gemm, cudaFuncAttributeMaxDynamicSharedMemorySize,
                         HG_SMEM);

    const float scl = 0.08838834764831845f;  // 1/sqrt(128)

    // modulation vector (shift | scale | gate)
    mod_kernel<<<(3 * HIDDEN + 3) / 4, 128>>>(vec, mod_w, mod_b);
    // layernorm + modulate all 4372 unique rows
    ln_mod_kernel<<<NROWS, 256>>>(x, concepts);
    // GEMM1: h = xm @ w1^T + b1   [4372 x 10752]  (HMMA)
    hmma_gemm<<<dim3(W1OUT / 128, (NROWS + 127) / 128, 1), 256, HG_SMEM>>>(
        xm, HIDDEN, 0, w1, HIDDEN, 0, hbuf, W1OUT, 0,
        NROWS, W1OUT, HIDDEN, 1.f, b1);
    // rmsnorm + rope; block2 K/V for image tokens derived from shared values
    attn_prep1<<<dim3(LX, NHEADS), 128>>>(pe, cpe, q_scale, k_scale);
    attn_prep2<<<dim3(NC, NHEADS), 128>>>(cpe, q_scale, k_scale);
    // block1 attention (HMMA)
    hmma_gemm<<<dim3(LX / 128, LX / 128, NHEADS), 256, HG_SMEM>>>(
        q1b, HDIM, (long long)LX * HDIM, k1b, HDIM, (long long)LX * HDIM,
        s1b, LX, (long long)LX * LX, LX, LX, HDIM, scl, nullptr);
    softmax_rows<<<NHEADS * LX, 256>>>(s1b, LX);
    hmma_gemm<<<dim3(1, LX / 128, NHEADS), 256, HG_SMEM>>>(
        s1b, LX, (long long)LX * LX, vt1b, LX, (long long)HDIM * LX,
        ccb, CCW, HDIM, LX, HDIM, LX, 1.f, nullptr);
    // block2 attention (20 queries over 4116 keys) — tiny, SIMT path
    sgemm_abt<<<dim3((LC + 127) / 128, 1, NHEADS), 256>>>(
        q2b, HDIM, (long long)NC * HDIM, k2b, HDIM, (long long)LC * HDIM,
        s2b, LC, (long long)NC * LC, NC, LC, HDIM, scl, nullptr);
    softmax_rows<<<NHEADS * NC, 256>>>(s2b, LC);
    sgemm_abt<<<dim3(1, 1, NHEADS), 256>>>(
        s2b, LC, (long long)NC * LC, vt2b, LC, (long long)HDIM * LC,
        ccb + (size_t)LX * CCW, CCW, HDIM, NC, HDIM, LC, 1.f, nullptr);
    // gelu on mlp half into concat buffer
    gelu_kernel<<<(unsigned)(((size_t)NROWS * MLPH + 255) / 256), 256>>>();
    // GEMM2: out = cc @ w2^T + b2   [4372 x 1536]  (HMMA)
    hmma_gemm<<<dim3(HIDDEN / 128, (NROWS + 127) / 128, 1), 256, HG_SMEM>>>(
        ccb, CCW, 0, w2, CCW, 0, outb, HIDDEN, 0,
        NROWS, HIDDEN, CCW, 1.f, b2);
    // residual + gate
    final_kernel<<<(unsigned)(((size_t)NROWS * HIDDEN + 255) / 256), 256>>>(
        x, concepts, out);
}